// round 1
// baseline (speedup 1.0000x reference)
#include <cuda_runtime.h>
#include <math.h>

// MoE fused kernel: gate(top-2 softmax) + layer1(+SiLU) + grouped layer2 +
// weighted combine + residual, all in one kernel. fp32 SIMT GEMM baseline.
//
// Shapes: x [B=2, C=256, THW=16384]; w1 [1024,256]; w2 [4,256,256];
// gate_w [4,256]. N tokens = 32768. Each CTA: 64 tokens, all 256 channels.

namespace {
constexpr int C        = 256;
constexpr int E        = 4;
constexpr int TM       = 64;            // tokens per CTA
constexpr int KB       = 16;            // k-chunk for weight staging
constexpr int THW      = 16 * 32 * 32;  // 16384
constexpr int NTOK     = 2 * THW;       // 32768
constexpr int NTHREADS = 256;

// shared memory layout (in floats)
constexpr int XS_OFF = 0;                  // x tile      [C][TM]
constexpr int HS_OFF = XS_OFF + C * TM;    // h tile      [C][TM]
constexpr int WK_OFF = HS_OFF + C * TM;    // weight chunk [KB][C]
constexpr int B1_OFF = WK_OFF + KB * C;    // b1          [E*C]
constexpr int B2_OFF = B1_OFF + E * C;     // b2          [E*C]
constexpr int GW_OFF = B2_OFF + E * C;     // gate_w      [E*C]
constexpr int GB_OFF = GW_OFF + E * C;     // gate_b      [4]
constexpr int LG_OFF = GB_OFF + 4;         // logits      [TM][E]
constexpr int WT_OFF = LG_OFF + TM * E;    // weights     [TM][E]
constexpr int SMEM_FLOATS = WT_OFF + TM * E;
constexpr int SMEM_BYTES  = SMEM_FLOATS * 4;
}  // namespace

// Register-blocked GEMM pass over the full K=C dimension.
// acc[8][8] += W[orow..orow+7 rows][:] * src[:][cols], where the 8 columns of
// this thread are {c0..c0+3, c1..c1+3}. Weight chunks are staged into smem
// k-major ([KB][C]) with a register prefetch of the next chunk.
__device__ __forceinline__ void gemm_pass(
    float acc[8][8],
    const float* __restrict__ Wg,    // global, [C out rows][C in cols]
    const float* __restrict__ src,   // smem, [C][TM]
    float* __restrict__ wk,          // smem, [KB][C]
    int tid, int orow, int c0, int c1)
{
  constexpr int NCH = C / KB;  // 16 chunks
  float4 rr[KB / 4];

  // prefetch chunk 0: thread tid owns out-row tid, 16 contiguous floats
  {
    const float4* gp = reinterpret_cast<const float4*>(Wg + (size_t)tid * C);
#pragma unroll
    for (int q = 0; q < KB / 4; ++q) rr[q] = gp[q];
  }

  for (int ch = 0; ch < NCH; ++ch) {
    __syncthreads();  // all threads done reading wk (prev chunk / prev pass)
#pragma unroll
    for (int q = 0; q < KB / 4; ++q) {
      wk[(q * 4 + 0) * C + tid] = rr[q].x;
      wk[(q * 4 + 1) * C + tid] = rr[q].y;
      wk[(q * 4 + 2) * C + tid] = rr[q].z;
      wk[(q * 4 + 3) * C + tid] = rr[q].w;
    }
    __syncthreads();  // chunk visible to all

    if (ch + 1 < NCH) {  // prefetch next chunk, overlaps with compute below
      const float4* gp =
          reinterpret_cast<const float4*>(Wg + (size_t)tid * C + (ch + 1) * KB);
#pragma unroll
      for (int q = 0; q < KB / 4; ++q) rr[q] = gp[q];
    }

    const float* s = src + ch * KB * TM;
#pragma unroll 4
    for (int k = 0; k < KB; ++k) {
      float4 a0  = *reinterpret_cast<const float4*>(wk + k * C + orow);
      float4 a1  = *reinterpret_cast<const float4*>(wk + k * C + orow + 4);
      float4 b0  = *reinterpret_cast<const float4*>(s + k * TM + c0);
      float4 b1v = *reinterpret_cast<const float4*>(s + k * TM + c1);
      float a[8]  = {a0.x, a0.y, a0.z, a0.w, a1.x, a1.y, a1.z, a1.w};
      float bb[8] = {b0.x, b0.y, b0.z, b0.w, b1v.x, b1v.y, b1v.z, b1v.w};
#pragma unroll
      for (int i = 0; i < 8; ++i)
#pragma unroll
        for (int j = 0; j < 8; ++j)
          acc[i][j] = fmaf(a[i], bb[j], acc[i][j]);
    }
  }
}

__global__ __launch_bounds__(NTHREADS, 1)
void moe_fused_kernel(const float* __restrict__ x,
                      const float* __restrict__ gate_w,
                      const float* __restrict__ gate_b,
                      const float* __restrict__ w1,
                      const float* __restrict__ b1,
                      const float* __restrict__ w2,
                      const float* __restrict__ b2,
                      float* __restrict__ out)
{
  extern __shared__ float sm[];
  float* xs  = sm + XS_OFF;
  float* hs  = sm + HS_OFF;
  float* wk  = sm + WK_OFF;
  float* b1s = sm + B1_OFF;
  float* b2s = sm + B2_OFF;
  float* gws = sm + GW_OFF;
  float* gbs = sm + GB_OFF;
  float* lg  = sm + LG_OFF;
  float* wts = sm + WT_OFF;

  const int tid    = threadIdx.x;
  const int token0 = blockIdx.x * TM;       // 16384 % 64 == 0: never crosses batch
  const int bidx   = token0 / THW;
  const int s0     = token0 % THW;
  const float* xg  = x   + (size_t)bidx * C * THW + s0;
  float*       og  = out + (size_t)bidx * C * THW + s0;

  // ---- stage x tile: xs[c][t], vectorized & coalesced --------------------
#pragma unroll
  for (int r = 0; r < (C * TM / 4) / NTHREADS; ++r) {  // 16 iters
    int idx = r * NTHREADS + tid;
    int c   = idx >> 4;        // 16 float4 per 64-token row
    int t4  = idx & 15;
    float4 v = *reinterpret_cast<const float4*>(xg + (size_t)c * THW + t4 * 4);
    *reinterpret_cast<float4*>(xs + c * TM + t4 * 4) = v;
  }
  // ---- stage biases + gate weights ---------------------------------------
#pragma unroll
  for (int r = 0; r < (E * C) / NTHREADS; ++r) {  // 4 iters
    int i = r * NTHREADS + tid;
    b1s[i] = b1[i];
    b2s[i] = b2[i];
    gws[i] = gate_w[i];
  }
  if (tid < E) gbs[tid] = gate_b[tid];
  __syncthreads();

  // ---- gate logits: thread -> (token = tid/4, expert = tid%4) ------------
  {
    int t = tid >> 2, e = tid & 3;
    float acc = gbs[e];
    const float* gw = gws + e * C;
#pragma unroll 8
    for (int c = 0; c < C; ++c) acc = fmaf(gw[c], xs[c * TM + t], acc);
    lg[t * E + e] = acc;
  }
  __syncthreads();

  // ---- top-2 of 4 + softmax, scattered into E slots ----------------------
  if (tid < TM) {
    float l0 = lg[tid * E + 0], l1 = lg[tid * E + 1];
    float l2 = lg[tid * E + 2], l3 = lg[tid * E + 3];
    float v1 = l0; int i1 = 0;
    if (l1 > v1) { v1 = l1; i1 = 1; }
    if (l2 > v1) { v1 = l2; i1 = 2; }
    if (l3 > v1) { v1 = l3; i1 = 3; }
    float v2 = -3.402823e38f; int i2 = 0;
    if (i1 != 0 && l0 > v2) { v2 = l0; i2 = 0; }
    if (i1 != 1 && l1 > v2) { v2 = l1; i2 = 1; }
    if (i1 != 2 && l2 > v2) { v2 = l2; i2 = 2; }
    if (i1 != 3 && l3 > v2) { v2 = l3; i2 = 3; }
    float e2v = __expf(v2 - v1);
    float inv = 1.0f / (1.0f + e2v);
    wts[tid * E + 0] = 0.f; wts[tid * E + 1] = 0.f;
    wts[tid * E + 2] = 0.f; wts[tid * E + 3] = 0.f;
    wts[tid * E + i1] = inv;
    wts[tid * E + i2] = e2v * inv;
  }
  // (no sync needed here: gemm_pass begins with two barriers before any read)

  // ---- main: per-expert layer1 -> SiLU*gate -> layer2 (accumulated) ------
  const int ty   = tid >> 3;       // 0..31
  const int tx   = tid & 7;        // 0..7
  const int orow = ty * 8;         // 8 output rows
  const int c0   = tx * 4;         // cols {c0..c0+3, c1..c1+3} (bank-friendly)
  const int c1   = 32 + tx * 4;

  float acc2[8][8];
#pragma unroll
  for (int i = 0; i < 8; ++i)
#pragma unroll
    for (int j = 0; j < 8; ++j) acc2[i][j] = 0.f;

  for (int e = 0; e < E; ++e) {
    // layer1 GEMM for this expert
    float acc1[8][8];
#pragma unroll
    for (int i = 0; i < 8; ++i)
#pragma unroll
      for (int j = 0; j < 8; ++j) acc1[i][j] = 0.f;

    gemm_pass(acc1, w1 + (size_t)e * C * C, xs, wk, tid, orow, c0, c1);

    // epilogue: +b1, SiLU, scale columns by gate weight, write to hs
    float wloc[8];
#pragma unroll
    for (int j = 0; j < 8; ++j) {
      int col = (j < 4) ? (c0 + j) : (c1 + j - 4);
      wloc[j] = wts[col * E + e];
    }
#pragma unroll
    for (int i = 0; i < 8; ++i) {
      float bias = b1s[e * C + orow + i];
#pragma unroll
      for (int j = 0; j < 8; ++j) {
        float h = acc1[i][j] + bias;
        h = h * (1.0f / (1.0f + __expf(-h)));  // SiLU
        int col = (j < 4) ? (c0 + j) : (c1 + j - 4);
        hs[(orow + i) * TM + col] = h * wloc[j];
      }
    }
    // layer2 GEMM, accumulated across experts (weight already folded into hs).
    // gemm_pass's leading barriers order the hs writes above vs. its reads.
    gemm_pass(acc2, w2 + (size_t)e * C * C, hs, wk, tid, orow, c0, c1);
  }

  // ---- final epilogue: + sum_e wt_e*b2_e + residual, vectorized store ----
#pragma unroll
  for (int i = 0; i < 8; ++i) {
    int oc = orow + i;
    float oa[4], ob[4];
#pragma unroll
    for (int j = 0; j < 8; ++j) {
      int col = (j < 4) ? (c0 + j) : (c1 + j - 4);
      float bt = 0.f;
#pragma unroll
      for (int ee = 0; ee < E; ++ee)
        bt = fmaf(wts[col * E + ee], b2s[ee * C + oc], bt);
      float v = acc2[i][j] + bt + xs[oc * TM + col];
      if (j < 4) oa[j] = v; else ob[j - 4] = v;
    }
    *reinterpret_cast<float4*>(og + (size_t)oc * THW + c0) =
        make_float4(oa[0], oa[1], oa[2], oa[3]);
    *reinterpret_cast<float4*>(og + (size_t)oc * THW + c1) =
        make_float4(ob[0], ob[1], ob[2], ob[3]);
  }
}

extern "C" void kernel_launch(void* const* d_in, const int* in_sizes, int n_in,
                              void* d_out, int out_size) {
  const float* x      = (const float*)d_in[0];
  const float* gate_w = (const float*)d_in[1];
  const float* gate_b = (const float*)d_in[2];
  const float* w1     = (const float*)d_in[3];
  const float* b1     = (const float*)d_in[4];
  const float* w2     = (const float*)d_in[5];
  const float* b2     = (const float*)d_in[6];
  float* out          = (float*)d_out;

  cudaFuncSetAttribute(moe_fused_kernel,
                       cudaFuncAttributeMaxDynamicSharedMemorySize, SMEM_BYTES);

  dim3 grid(NTOK / TM);  // 512 CTAs
  moe_fused_kernel<<<grid, NTHREADS, SMEM_BYTES>>>(
      x, gate_w, gate_b, w1, b1, w2, b2, out);
}

// round 5
// speedup vs baseline: 4.6455x; 4.6455x over previous
#include <cuda_runtime.h>
#include <cuda_bf16.h>
#include <cstdint>
#include <math.h>

// ===========================================================================
// Fused MoE: gate(top-2 softmax, fp32) + layer1(+SiLU) + grouped layer2 +
// weighted combine + residual.  GEMMs in bf16 via mma.sync.m16n8k16 (base
// sm_103 target -- no tcgen05).  Weights pre-swizzled to smem images by a
// prologue kernel; staged with double-buffered cp.async.
// ===========================================================================

namespace {
constexpr int C    = 256;
constexpr int E    = 4;
constexpr int THW  = 16 * 32 * 32;   // 16384
constexpr int NTOK = 2 * THW;        // 32768
constexpr int TM   = 64;             // tokens per CTA
constexpr int NCTA = NTOK / TM;      // 512
constexpr int NTHR = 256;            // 8 warps

constexpr int NSTAGE      = 16;      // e*4 + {g1k0, g1k1, g2k0, g2k1}
constexpr int STAGE_BYTES = 65536;   // 256 rows x 128 k x bf16 (swizzled)

// shared memory byte offsets
constexpr int SM_WBUF0 = 0;
constexpr int SM_WBUF1 = 65536;
constexpr int SM_XS    = 131072;           // x bf16 [64][256] swizzled
constexpr int SM_HS    = 163840;           // h bf16 [64][256] swizzled
constexpr int SM_GW    = 196608;           // gate_w fp32 [1024]
constexpr int SM_B1    = 200704;           // b1 fp32 [1024]
constexpr int SM_B2    = 204800;           // b2 fp32 [1024]
constexpr int SM_SP    = 208896;           // logit partials [4][64][4] fp32
constexpr int SM_WT    = 212992;           // gate weights [64][4] fp32
constexpr int SM_TOTAL = 214016;
}  // namespace

__device__ __align__(16) unsigned char g_wimg[NSTAGE * STAGE_BYTES];

// ------------------------------ helpers -----------------------------------
__device__ __forceinline__ uint32_t smem_u32(const void* p) {
  uint32_t a;
  asm("{ .reg .u64 t; cvta.to.shared.u64 t, %1; cvt.u32.u64 %0, t; }"
      : "=r"(a) : "l"(p));
  return a;
}
__device__ __forceinline__ void ldsm4(uint32_t* r, uint32_t addr) {
  asm volatile("ldmatrix.sync.aligned.m8n8.x4.shared.b16 {%0,%1,%2,%3}, [%4];"
               : "=r"(r[0]), "=r"(r[1]), "=r"(r[2]), "=r"(r[3]) : "r"(addr));
}
__device__ __forceinline__ void mma16816(float* d, const uint32_t* a,
                                         const uint32_t* b) {
  asm volatile(
      "mma.sync.aligned.m16n8k16.row.col.f32.bf16.bf16.f32 "
      "{%0,%1,%2,%3}, {%4,%5,%6,%7}, {%8,%9}, {%0,%1,%2,%3};"
      : "+f"(d[0]), "+f"(d[1]), "+f"(d[2]), "+f"(d[3])
      : "r"(a[0]), "r"(a[1]), "r"(a[2]), "r"(a[3]), "r"(b[0]), "r"(b[1]));
}
__device__ __forceinline__ void cp16(uint32_t dst, const void* src) {
  asm volatile("cp.async.cg.shared.global [%0], [%1], 16;"
               :: "r"(dst), "l"(src));
}
__device__ __forceinline__ void cp_commit() {
  asm volatile("cp.async.commit_group;" ::: "memory");
}
template <int N>
__device__ __forceinline__ void cp_wait() {
  asm volatile("cp.async.wait_group %0;" :: "n"(N) : "memory");
}
__device__ __forceinline__ uint32_t pack_bf2(float a, float b) {
  __nv_bfloat162 t = __floats2bfloat162_rn(a, b);  // .x = a (low)
  return *reinterpret_cast<uint32_t*>(&t);
}

// One 128-k chunk of a [64 x 256-out] GEMM for this warp's (wm, wn) tile.
// A: smem bf16 [64 rows][256 k], 512B rows, chunk swizzle kc^(row&7).
// B: weight stage buf [256 rows(n)][128 k], 256B rows, same swizzle.
__device__ __forceinline__ void run_chunk(float (&acc)[16][4],
                                          uint32_t asrc, int kbase,
                                          uint32_t wbuf, int wm, int wn,
                                          int lane) {
  const int r  = lane & 7;
  const int mi = lane >> 3;
  uint32_t a[8][4];
#pragma unroll
  for (int kst = 0; kst < 8; ++kst) {
    int row = wm * 16 + (mi & 1) * 8 + r;
    int kc  = (kbase >> 3) + kst * 2 + (mi >> 1);
    ldsm4(a[kst], asrc + row * 512 + ((kc ^ r) << 4));
  }
#pragma unroll
  for (int nt = 0; nt < 16; ++nt) {
    const int n0 = wn * 128 + nt * 8;
#pragma unroll
    for (int kq = 0; kq < 4; ++kq) {
      uint32_t b[4];
      int kc = kq * 4 + mi;
      ldsm4(b, wbuf + (n0 + r) * 256 + ((kc ^ r) << 4));
      mma16816(acc[nt], a[2 * kq],     b);
      mma16816(acc[nt], a[2 * kq + 1], b + 2);
    }
  }
}

// ---------------------------------------------------------------------------
// Prologue: build bf16 swizzled weight images (16 stages x 256 rows x 128 k).
// ---------------------------------------------------------------------------
__global__ void prep_weights(const float* __restrict__ w1,
                             const float* __restrict__ w2) {
  int idx = blockIdx.x * blockDim.x + threadIdx.x;  // 65536 threads
  int s  = idx >> 12;          // stage
  int r  = (idx >> 4) & 255;   // row (out/hidden channel)
  int kc = idx & 15;           // 16B chunk within 128-k row
  int e = s >> 2, c = s & 3;
  const float* src;
  if (c < 2) src = w1 + (size_t)(e * 256 + r) * 256 + c * 128 + kc * 8;
  else       src = w2 + (size_t)e * 65536 + (size_t)r * 256 + (c - 2) * 128 + kc * 8;
  float4 v0 = *reinterpret_cast<const float4*>(src);
  float4 v1 = *reinterpret_cast<const float4*>(src + 4);
  uint4 pk;
  pk.x = pack_bf2(v0.x, v0.y);
  pk.y = pack_bf2(v0.z, v0.w);
  pk.z = pack_bf2(v1.x, v1.y);
  pk.w = pack_bf2(v1.z, v1.w);
  *reinterpret_cast<uint4*>(g_wimg + (size_t)s * STAGE_BYTES + r * 256 +
                            ((kc ^ (r & 7)) << 4)) = pk;
}

// ---------------------------------------------------------------------------
// Main fused kernel.
// ---------------------------------------------------------------------------
__global__ __launch_bounds__(NTHR, 1)
void moe_mma_kernel(const float* __restrict__ x,
                    const float* __restrict__ gate_w,
                    const float* __restrict__ gate_b,
                    const float* __restrict__ b1,
                    const float* __restrict__ b2,
                    float* __restrict__ out) {
  extern __shared__ __align__(16) unsigned char smraw[];
  const uint32_t smb = smem_u32(smraw);
  float* gws  = reinterpret_cast<float*>(smraw + SM_GW);
  float* b1s  = reinterpret_cast<float*>(smraw + SM_B1);
  float* b2s  = reinterpret_cast<float*>(smraw + SM_B2);
  float* sp   = reinterpret_cast<float*>(smraw + SM_SP);
  float* wts  = reinterpret_cast<float*>(smraw + SM_WT);

  const int tid  = threadIdx.x;
  const int lane = tid & 31;
  const int wid  = tid >> 5;
  const int wm   = wid & 3;    // token block (16 rows)
  const int wn   = wid >> 2;   // out-col block (128 cols)

  const int token0 = blockIdx.x * TM;
  const int bidx   = token0 / THW;
  const int s0     = token0 % THW;
  const float* xb = x   + (size_t)bidx * C * THW + s0;
  float*       ob = out + (size_t)bidx * C * THW + s0;

  // --- kick stage 0 weight copy immediately -------------------------------
  {
    const unsigned char* src = g_wimg;
#pragma unroll
    for (int it = 0; it < 16; ++it) {
      int off = it * 4096 + tid * 16;
      cp16(smb + SM_WBUF0 + off, src + off);
    }
    cp_commit();
  }

  // --- stage gate_w / b1 / b2 ---------------------------------------------
#pragma unroll
  for (int rr = 0; rr < 4; ++rr) {
    int i = rr * NTHR + tid;
    gws[i] = gate_w[i];
    b1s[i] = b1[i];
    b2s[i] = b2[i];
  }
  __syncthreads();

  // --- x staging (fp32->bf16, swizzled) + fp32 gate logit partials --------
  {
    const int t  = tid & 63;
    const int cp = tid >> 6;  // 0..3
    float l[4] = {0.f, 0.f, 0.f, 0.f};
    const float* gx = xb + t;
#pragma unroll
    for (int it = 0; it < 32; ++it) {
      int c0 = it * 8 + cp * 2;
      float v0 = __ldg(gx + (size_t)c0 * THW);
      float v1 = __ldg(gx + (size_t)(c0 + 1) * THW);
#pragma unroll
      for (int e = 0; e < 4; ++e)
        l[e] = fmaf(gws[e * 256 + c0], v0, fmaf(gws[e * 256 + c0 + 1], v1, l[e]));
      uint32_t pk = pack_bf2(v0, v1);
      uint32_t off = t * 512 + (((c0 >> 3) ^ (t & 7)) << 4) + (c0 & 7) * 2;
      *reinterpret_cast<uint32_t*>(smraw + SM_XS + off) = pk;
    }
#pragma unroll
    for (int e = 0; e < 4; ++e) sp[cp * 256 + t * 4 + e] = l[e];
  }
  __syncthreads();

  // --- logits reduce + top-2 softmax --------------------------------------
  if (tid < 64) {
    float l[4];
#pragma unroll
    for (int e = 0; e < 4; ++e)
      l[e] = sp[tid * 4 + e] + sp[256 + tid * 4 + e] + sp[512 + tid * 4 + e] +
             sp[768 + tid * 4 + e] + __ldg(gate_b + e);
    float v1 = l[0]; int i1 = 0;
    if (l[1] > v1) { v1 = l[1]; i1 = 1; }
    if (l[2] > v1) { v1 = l[2]; i1 = 2; }
    if (l[3] > v1) { v1 = l[3]; i1 = 3; }
    float v2 = -3.402823e38f; int i2 = 0;
#pragma unroll
    for (int e = 0; e < 4; ++e)
      if (e != i1 && l[e] > v2) { v2 = l[e]; i2 = e; }
    float e2  = __expf(v2 - v1);
    float inv = 1.0f / (1.0f + e2);
    wts[tid * 4 + 0] = 0.f; wts[tid * 4 + 1] = 0.f;
    wts[tid * 4 + 2] = 0.f; wts[tid * 4 + 3] = 0.f;
    wts[tid * 4 + i1] = inv;
    wts[tid * 4 + i2] = e2 * inv;
  }
  __syncthreads();

  // --- main pipelined loop over 16 weight stages --------------------------
  float acc1[16][4], acc2[16][4];
#pragma unroll
  for (int nt = 0; nt < 16; ++nt)
#pragma unroll
    for (int j = 0; j < 4; ++j) acc2[nt][j] = 0.f;

#pragma unroll 1
  for (int s = 0; s < NSTAGE; ++s) {
    if (s + 1 < NSTAGE) {  // prefetch next stage into the other buffer
      const unsigned char* src = g_wimg + (size_t)(s + 1) * STAGE_BYTES;
      uint32_t dst = smb + (((s + 1) & 1) ? SM_WBUF1 : SM_WBUF0);
#pragma unroll
      for (int it = 0; it < 16; ++it) {
        int off = it * 4096 + tid * 16;
        cp16(dst + off, src + off);
      }
      cp_commit();
      cp_wait<1>();
    } else {
      cp_wait<0>();
    }
    __syncthreads();

    const int c = s & 3, e = s >> 2;
    const uint32_t wbuf = smb + ((s & 1) ? SM_WBUF1 : SM_WBUF0);

    if (c == 0) {
#pragma unroll
      for (int nt = 0; nt < 16; ++nt)
#pragma unroll
        for (int j = 0; j < 4; ++j) acc1[nt][j] = 0.f;
      run_chunk(acc1, smb + SM_XS, 0, wbuf, wm, wn, lane);
    } else if (c == 1) {
      run_chunk(acc1, smb + SM_XS, 128, wbuf, wm, wn, lane);
      // h epilogue: +b1, SiLU, x gate weight, pack bf16 -> hs
      const int tok1 = wm * 16 + (lane >> 2);
      const int tok2 = tok1 + 8;
      const float wt1 = wts[tok1 * 4 + e];
      const float wt2 = wts[tok2 * 4 + e];
#pragma unroll
      for (int nt = 0; nt < 16; ++nt) {
        int n = wn * 128 + nt * 8 + (lane & 3) * 2;
        float ba = b1s[e * 256 + n], bb = b1s[e * 256 + n + 1];
        float h0 = acc1[nt][0] + ba, h1 = acc1[nt][1] + bb;
        float h2 = acc1[nt][2] + ba, h3 = acc1[nt][3] + bb;
        h0 = h0 * (1.0f / (1.0f + __expf(-h0))) * wt1;
        h1 = h1 * (1.0f / (1.0f + __expf(-h1))) * wt1;
        h2 = h2 * (1.0f / (1.0f + __expf(-h2))) * wt2;
        h3 = h3 * (1.0f / (1.0f + __expf(-h3))) * wt2;
        uint32_t o1 = tok1 * 512 + (((n >> 3) ^ (tok1 & 7)) << 4) + (n & 7) * 2;
        uint32_t o2 = tok2 * 512 + (((n >> 3) ^ (tok2 & 7)) << 4) + (n & 7) * 2;
        *reinterpret_cast<uint32_t*>(smraw + SM_HS + o1) = pack_bf2(h0, h1);
        *reinterpret_cast<uint32_t*>(smraw + SM_HS + o2) = pack_bf2(h2, h3);
      }
    } else if (c == 2) {
      run_chunk(acc2, smb + SM_HS, 0, wbuf, wm, wn, lane);
    } else {
      run_chunk(acc2, smb + SM_HS, 128, wbuf, wm, wn, lane);
    }
    __syncthreads();
  }

  // --- final epilogue: acc2 -> smem (coalescing relay) -> global ----------
  float* d2s = reinterpret_cast<float*>(smraw);  // overlays weight buffers
  {
    const int tok1 = wm * 16 + (lane >> 2);
    const int tok2 = tok1 + 8;
#pragma unroll
    for (int nt = 0; nt < 16; ++nt) {
      int n = wn * 128 + nt * 8 + (lane & 3) * 2;
      *reinterpret_cast<float2*>(d2s + tok1 * 258 + n) =
          make_float2(acc2[nt][0], acc2[nt][1]);
      *reinterpret_cast<float2*>(d2s + tok2 * 258 + n) =
          make_float2(acc2[nt][2], acc2[nt][3]);
    }
  }
  __syncthreads();
  {
    const int t  = tid & 63;
    const int cg = tid >> 6;
    const float w0 = wts[t * 4 + 0], w1w = wts[t * 4 + 1];
    const float w2w = wts[t * 4 + 2], w3 = wts[t * 4 + 3];
#pragma unroll 4
    for (int i = 0; i < 64; ++i) {
      int ch = i * 4 + cg;
      float v = d2s[t * 258 + ch]
              + w0  * b2s[ch]       + w1w * b2s[256 + ch]
              + w2w * b2s[512 + ch] + w3  * b2s[768 + ch]
              + __ldg(xb + (size_t)ch * THW + t);
      ob[(size_t)ch * THW + t] = v;
    }
  }
}

// ---------------------------------------------------------------------------
extern "C" void kernel_launch(void* const* d_in, const int* in_sizes, int n_in,
                              void* d_out, int out_size) {
  const float* x      = (const float*)d_in[0];
  const float* gate_w = (const float*)d_in[1];
  const float* gate_b = (const float*)d_in[2];
  const float* w1     = (const float*)d_in[3];
  const float* b1     = (const float*)d_in[4];
  const float* w2     = (const float*)d_in[5];
  const float* b2     = (const float*)d_in[6];
  float* out          = (float*)d_out;
  (void)in_sizes; (void)n_in; (void)out_size;

  prep_weights<<<256, 256>>>(w1, w2);

  cudaFuncSetAttribute(moe_mma_kernel,
                       cudaFuncAttributeMaxDynamicSharedMemorySize, SM_TOTAL);
  moe_mma_kernel<<<NCTA, NTHR, SM_TOTAL>>>(x, gate_w, gate_b, b1, b2, out);
}

// round 7
// speedup vs baseline: 6.0832x; 1.3095x over previous
#include <cuda_runtime.h>
#include <cuda_bf16.h>
#include <cstdint>
#include <math.h>

// ===========================================================================
// Fused MoE: gate(top-2 softmax, fp32) + layer1(+SiLU) + grouped layer2 +
// weighted combine + residual.  GEMMs in bf16 via mma.sync.m16n8k16.
// R6: 16 warps / 32x32 warp tiles (was 8 warps / 16x128) -> less LDSM traffic
// per MMA and 2x the warps to hide LDS latency.
// ===========================================================================

namespace {
constexpr int C    = 256;
constexpr int E    = 4;
constexpr int THW  = 16 * 32 * 32;   // 16384
constexpr int NTOK = 2 * THW;        // 32768
constexpr int TM   = 64;             // tokens per CTA
constexpr int NCTA = NTOK / TM;      // 512
constexpr int NTHR = 512;            // 16 warps

constexpr int NSTAGE      = 16;      // e*4 + {g1k0, g1k1, g2k0, g2k1}
constexpr int STAGE_BYTES = 65536;   // 256 rows x 128 k x bf16 (swizzled)

// shared memory byte offsets
constexpr int SM_WBUF0 = 0;
constexpr int SM_WBUF1 = 65536;
constexpr int SM_XS    = 131072;           // x bf16 [64][256] swizzled (32 KB)
constexpr int SM_HS    = 163840;           // h bf16 [64][256] swizzled (32 KB)
constexpr int SM_GW    = 196608;           // gate_w fp32 [1024]
constexpr int SM_B1    = 200704;           // b1 fp32 [1024]
constexpr int SM_B2    = 204800;           // b2 fp32 [1024]
constexpr int SM_SP    = 208896;           // logit partials [8][64][4] fp32
constexpr int SM_WT    = 217088;           // gate weights [64][4] fp32
constexpr int SM_TOTAL = 218112;
}  // namespace

__device__ __align__(16) unsigned char g_wimg[NSTAGE * STAGE_BYTES];

// ------------------------------ helpers -----------------------------------
__device__ __forceinline__ uint32_t smem_u32(const void* p) {
  uint32_t a;
  asm("{ .reg .u64 t; cvta.to.shared.u64 t, %1; cvt.u32.u64 %0, t; }"
      : "=r"(a) : "l"(p));
  return a;
}
__device__ __forceinline__ void ldsm4(uint32_t* r, uint32_t addr) {
  asm volatile("ldmatrix.sync.aligned.m8n8.x4.shared.b16 {%0,%1,%2,%3}, [%4];"
               : "=r"(r[0]), "=r"(r[1]), "=r"(r[2]), "=r"(r[3]) : "r"(addr));
}
__device__ __forceinline__ void mma16816(float* d, const uint32_t* a,
                                         const uint32_t* b) {
  asm volatile(
      "mma.sync.aligned.m16n8k16.row.col.f32.bf16.bf16.f32 "
      "{%0,%1,%2,%3}, {%4,%5,%6,%7}, {%8,%9}, {%0,%1,%2,%3};"
      : "+f"(d[0]), "+f"(d[1]), "+f"(d[2]), "+f"(d[3])
      : "r"(a[0]), "r"(a[1]), "r"(a[2]), "r"(a[3]), "r"(b[0]), "r"(b[1]));
}
__device__ __forceinline__ void cp16(uint32_t dst, const void* src) {
  asm volatile("cp.async.cg.shared.global [%0], [%1], 16;"
               :: "r"(dst), "l"(src));
}
__device__ __forceinline__ void cp_commit() {
  asm volatile("cp.async.commit_group;" ::: "memory");
}
template <int N>
__device__ __forceinline__ void cp_wait() {
  asm volatile("cp.async.wait_group %0;" :: "n"(N) : "memory");
}
__device__ __forceinline__ uint32_t pack_bf2(float a, float b) {
  __nv_bfloat162 t = __floats2bfloat162_rn(a, b);  // .x = a (low)
  return *reinterpret_cast<uint32_t*>(&t);
}

// One 128-k chunk: warp tile M=32 (tokens), N=32 (out-channels), K=128.
// A: smem bf16 [64 rows][256 k], 512B rows, swizzle kc^(row&7).
// B: stage buf [256 rows(n)][128 k], 256B rows, same swizzle.
// kq-outer keeps the A working set at 16 regs.
__device__ __forceinline__ void run_chunk(float (&acc)[2][4][4],
                                          uint32_t asrc, int kbase,
                                          uint32_t wbuf, int wm, int wn,
                                          int lane) {
  const int r  = lane & 7;
  const int mi = lane >> 3;
#pragma unroll
  for (int kq = 0; kq < 4; ++kq) {
    uint32_t a[2][2][4];
#pragma unroll
    for (int mt = 0; mt < 2; ++mt)
#pragma unroll
      for (int ks = 0; ks < 2; ++ks) {
        int row = wm * 32 + mt * 16 + (mi & 1) * 8 + r;
        int kc  = (kbase >> 3) + (kq * 2 + ks) * 2 + (mi >> 1);
        ldsm4(a[mt][ks], asrc + row * 512 + ((kc ^ r) << 4));
      }
#pragma unroll
    for (int nt = 0; nt < 4; ++nt) {
      uint32_t b[4];
      int kc = kq * 4 + mi;
      ldsm4(b, wbuf + (wn * 32 + nt * 8 + r) * 256 + ((kc ^ r) << 4));
#pragma unroll
      for (int mt = 0; mt < 2; ++mt) {
        mma16816(acc[mt][nt], a[mt][0], b);
        mma16816(acc[mt][nt], a[mt][1], b + 2);
      }
    }
  }
}

// ---------------------------------------------------------------------------
// Prologue: build bf16 swizzled weight images (16 stages x 256 rows x 128 k).
// ---------------------------------------------------------------------------
__global__ void prep_weights(const float* __restrict__ w1,
                             const float* __restrict__ w2) {
  int idx = blockIdx.x * blockDim.x + threadIdx.x;  // 65536 threads
  int s  = idx >> 12;          // stage
  int r  = (idx >> 4) & 255;   // row (out/hidden channel)
  int kc = idx & 15;           // 16B chunk within 128-k row
  int e = s >> 2, c = s & 3;
  const float* src;
  if (c < 2) src = w1 + (size_t)(e * 256 + r) * 256 + c * 128 + kc * 8;
  else       src = w2 + (size_t)e * 65536 + (size_t)r * 256 + (c - 2) * 128 + kc * 8;
  float4 v0 = *reinterpret_cast<const float4*>(src);
  float4 v1 = *reinterpret_cast<const float4*>(src + 4);
  uint4 pk;
  pk.x = pack_bf2(v0.x, v0.y);
  pk.y = pack_bf2(v0.z, v0.w);
  pk.z = pack_bf2(v1.x, v1.y);
  pk.w = pack_bf2(v1.z, v1.w);
  *reinterpret_cast<uint4*>(g_wimg + (size_t)s * STAGE_BYTES + r * 256 +
                            ((kc ^ (r & 7)) << 4)) = pk;
}

// ---------------------------------------------------------------------------
// Main fused kernel.
// ---------------------------------------------------------------------------
__global__ __launch_bounds__(NTHR, 1)
void moe_mma_kernel(const float* __restrict__ x,
                    const float* __restrict__ gate_w,
                    const float* __restrict__ gate_b,
                    const float* __restrict__ b1,
                    const float* __restrict__ b2,
                    float* __restrict__ out) {
  extern __shared__ __align__(16) unsigned char smraw[];
  const uint32_t smb = smem_u32(smraw);
  float* gws  = reinterpret_cast<float*>(smraw + SM_GW);
  float* b1s  = reinterpret_cast<float*>(smraw + SM_B1);
  float* b2s  = reinterpret_cast<float*>(smraw + SM_B2);
  float* sp   = reinterpret_cast<float*>(smraw + SM_SP);
  float* wts  = reinterpret_cast<float*>(smraw + SM_WT);

  const int tid  = threadIdx.x;
  const int lane = tid & 31;
  const int wid  = tid >> 5;
  const int wm   = wid & 1;    // token block (32 rows)
  const int wn   = wid >> 1;   // out-col block (32 cols), 0..7

  const int token0 = blockIdx.x * TM;
  const int bidx   = token0 / THW;
  const int s0     = token0 % THW;
  const float* xb = x   + (size_t)bidx * C * THW + s0;
  float*       ob = out + (size_t)bidx * C * THW + s0;

  // --- kick stage 0 weight copy immediately -------------------------------
  {
    const unsigned char* src = g_wimg;
#pragma unroll
    for (int it = 0; it < 8; ++it) {
      int off = it * 8192 + tid * 16;
      cp16(smb + SM_WBUF0 + off, src + off);
    }
    cp_commit();
  }

  // --- stage gate_w / b1 / b2 ---------------------------------------------
#pragma unroll
  for (int rr = 0; rr < 2; ++rr) {
    int i = rr * NTHR + tid;
    gws[i] = gate_w[i];
    b1s[i] = b1[i];
    b2s[i] = b2[i];
  }
  __syncthreads();

  // --- x staging (fp32->bf16, swizzled) + fp32 gate logit partials --------
  {
    const int t   = tid & 63;
    const int cpg = tid >> 6;  // 0..7
    float l[4] = {0.f, 0.f, 0.f, 0.f};
    const float* gx = xb + t;
#pragma unroll
    for (int it = 0; it < 16; ++it) {
      int c0 = it * 16 + cpg * 2;
      float v0 = __ldg(gx + (size_t)c0 * THW);
      float v1 = __ldg(gx + (size_t)(c0 + 1) * THW);
#pragma unroll
      for (int e = 0; e < 4; ++e)
        l[e] = fmaf(gws[e * 256 + c0], v0, fmaf(gws[e * 256 + c0 + 1], v1, l[e]));
      uint32_t pk = pack_bf2(v0, v1);
      uint32_t off = t * 512 + (((c0 >> 3) ^ (t & 7)) << 4) + (c0 & 7) * 2;
      *reinterpret_cast<uint32_t*>(smraw + SM_XS + off) = pk;
    }
#pragma unroll
    for (int e = 0; e < 4; ++e) sp[cpg * 256 + t * 4 + e] = l[e];
  }
  __syncthreads();

  // --- logits reduce + top-2 softmax --------------------------------------
  if (tid < 64) {
    float l[4];
#pragma unroll
    for (int e = 0; e < 4; ++e) {
      float s = __ldg(gate_b + e);
#pragma unroll
      for (int g = 0; g < 8; ++g) s += sp[g * 256 + tid * 4 + e];
      l[e] = s;
    }
    float v1 = l[0]; int i1 = 0;
    if (l[1] > v1) { v1 = l[1]; i1 = 1; }
    if (l[2] > v1) { v1 = l[2]; i1 = 2; }
    if (l[3] > v1) { v1 = l[3]; i1 = 3; }
    float v2 = -3.402823e38f; int i2 = 0;
#pragma unroll
    for (int e = 0; e < 4; ++e)
      if (e != i1 && l[e] > v2) { v2 = l[e]; i2 = e; }
    float e2  = __expf(v2 - v1);
    float inv = 1.0f / (1.0f + e2);
    wts[tid * 4 + 0] = 0.f; wts[tid * 4 + 1] = 0.f;
    wts[tid * 4 + 2] = 0.f; wts[tid * 4 + 3] = 0.f;
    wts[tid * 4 + i1] = inv;
    wts[tid * 4 + i2] = e2 * inv;
  }
  __syncthreads();

  // --- main pipelined loop over 16 weight stages --------------------------
  float acc1[2][4][4], acc2[2][4][4];
#pragma unroll
  for (int mt = 0; mt < 2; ++mt)
#pragma unroll
    for (int nt = 0; nt < 4; ++nt)
#pragma unroll
      for (int j = 0; j < 4; ++j) acc2[mt][nt][j] = 0.f;

#pragma unroll 1
  for (int s = 0; s < NSTAGE; ++s) {
    if (s + 1 < NSTAGE) {  // prefetch next stage into the other buffer
      const unsigned char* src = g_wimg + (size_t)(s + 1) * STAGE_BYTES;
      uint32_t dst = smb + (((s + 1) & 1) ? SM_WBUF1 : SM_WBUF0);
#pragma unroll
      for (int it = 0; it < 8; ++it) {
        int off = it * 8192 + tid * 16;
        cp16(dst + off, src + off);
      }
      cp_commit();
      cp_wait<1>();
    } else {
      cp_wait<0>();
    }
    __syncthreads();

    const int c = s & 3, e = s >> 2;
    const uint32_t wbuf = smb + ((s & 1) ? SM_WBUF1 : SM_WBUF0);

    if (c == 0) {
#pragma unroll
      for (int mt = 0; mt < 2; ++mt)
#pragma unroll
        for (int nt = 0; nt < 4; ++nt)
#pragma unroll
          for (int j = 0; j < 4; ++j) acc1[mt][nt][j] = 0.f;
      run_chunk(acc1, smb + SM_XS, 0, wbuf, wm, wn, lane);
    } else if (c == 1) {
      run_chunk(acc1, smb + SM_XS, 128, wbuf, wm, wn, lane);
      // h epilogue: +b1, SiLU, x gate weight, pack bf16 -> hs
#pragma unroll
      for (int mt = 0; mt < 2; ++mt) {
        const int tok1 = wm * 32 + mt * 16 + (lane >> 2);
        const int tok2 = tok1 + 8;
        const float wt1 = wts[tok1 * 4 + e];
        const float wt2 = wts[tok2 * 4 + e];
#pragma unroll
        for (int nt = 0; nt < 4; ++nt) {
          int n = wn * 32 + nt * 8 + (lane & 3) * 2;
          float ba = b1s[e * 256 + n], bb = b1s[e * 256 + n + 1];
          float h0 = acc1[mt][nt][0] + ba, h1 = acc1[mt][nt][1] + bb;
          float h2 = acc1[mt][nt][2] + ba, h3 = acc1[mt][nt][3] + bb;
          h0 = h0 * (1.0f / (1.0f + __expf(-h0))) * wt1;
          h1 = h1 * (1.0f / (1.0f + __expf(-h1))) * wt1;
          h2 = h2 * (1.0f / (1.0f + __expf(-h2))) * wt2;
          h3 = h3 * (1.0f / (1.0f + __expf(-h3))) * wt2;
          uint32_t o1 = tok1 * 512 + (((n >> 3) ^ (tok1 & 7)) << 4) + (n & 7) * 2;
          uint32_t o2 = tok2 * 512 + (((n >> 3) ^ (tok2 & 7)) << 4) + (n & 7) * 2;
          *reinterpret_cast<uint32_t*>(smraw + SM_HS + o1) = pack_bf2(h0, h1);
          *reinterpret_cast<uint32_t*>(smraw + SM_HS + o2) = pack_bf2(h2, h3);
        }
      }
    } else if (c == 2) {
      run_chunk(acc2, smb + SM_HS, 0, wbuf, wm, wn, lane);
    } else {
      run_chunk(acc2, smb + SM_HS, 128, wbuf, wm, wn, lane);
    }
    __syncthreads();
  }

  // --- final epilogue: acc2 -> smem (coalescing relay) -> global ----------
  float* d2s = reinterpret_cast<float*>(smraw);  // overlays weight buffers
#pragma unroll
  for (int mt = 0; mt < 2; ++mt) {
    const int tok1 = wm * 32 + mt * 16 + (lane >> 2);
    const int tok2 = tok1 + 8;
#pragma unroll
    for (int nt = 0; nt < 4; ++nt) {
      int n = wn * 32 + nt * 8 + (lane & 3) * 2;
      *reinterpret_cast<float2*>(d2s + tok1 * 258 + n) =
          make_float2(acc2[mt][nt][0], acc2[mt][nt][1]);
      *reinterpret_cast<float2*>(d2s + tok2 * 258 + n) =
          make_float2(acc2[mt][nt][2], acc2[mt][nt][3]);
    }
  }
  __syncthreads();
  {
    const int t  = tid & 63;
    const int cg = tid >> 6;   // 0..7
    const float w0 = wts[t * 4 + 0], w1w = wts[t * 4 + 1];
    const float w2w = wts[t * 4 + 2], w3 = wts[t * 4 + 3];
#pragma unroll 4
    for (int i = 0; i < 32; ++i) {
      int ch = i * 8 + cg;
      float v = d2s[t * 258 + ch]
              + w0  * b2s[ch]       + w1w * b2s[256 + ch]
              + w2w * b2s[512 + ch] + w3  * b2s[768 + ch]
              + __ldg(xb + (size_t)ch * THW + t);
      ob[(size_t)ch * THW + t] = v;
    }
  }
}

// ---------------------------------------------------------------------------
extern "C" void kernel_launch(void* const* d_in, const int* in_sizes, int n_in,
                              void* d_out, int out_size) {
  const float* x      = (const float*)d_in[0];
  const float* gate_w = (const float*)d_in[1];
  const float* gate_b = (const float*)d_in[2];
  const float* b1     = (const float*)d_in[4];
  const float* w1     = (const float*)d_in[3];
  const float* w2     = (const float*)d_in[5];
  const float* b2     = (const float*)d_in[6];
  float* out          = (float*)d_out;
  (void)in_sizes; (void)n_in; (void)out_size;

  prep_weights<<<256, 256>>>(w1, w2);

  cudaFuncSetAttribute(moe_mma_kernel,
                       cudaFuncAttributeMaxDynamicSharedMemorySize, SM_TOTAL);
  moe_mma_kernel<<<NCTA, NTHR, SM_TOTAL>>>(x, gate_w, gate_b, b1, b2, out);
}

// round 8
// speedup vs baseline: 6.6446x; 1.0923x over previous
#include <cuda_runtime.h>
#include <cuda_bf16.h>
#include <cstdint>
#include <math.h>

// ===========================================================================
// Fused MoE: gate(top-2 softmax, fp32) + layer1(+SiLU) + grouped layer2 +
// weighted combine + residual.  bf16 mma.sync.m16n8k16.
// R8: TM=32 / 32KB weight stages -> 104.5KB smem -> 2 CTAs/SM for latency
// hiding (R7 was 1 CTA/SM, occ 25%, nothing saturated).
// ===========================================================================

namespace {
constexpr int C    = 256;
constexpr int E    = 4;
constexpr int THW  = 16 * 32 * 32;   // 16384
constexpr int NTOK = 2 * THW;        // 32768
constexpr int TM   = 32;             // tokens per CTA
constexpr int NCTA = NTOK / TM;      // 1024
constexpr int NTHR = 256;            // 8 warps

constexpr int NSTAGE      = 32;      // e*8 + phase (0-3: w1 kq, 4-7: w2 kq)
constexpr int STAGE_BYTES = 32768;   // 256 rows x 64 k x bf16 (swizzled)

// shared memory byte offsets
constexpr int SM_WBUF0 = 0;
constexpr int SM_WBUF1 = 32768;
constexpr int SM_XS    = 65536;            // x bf16 [32][256] swizzled (16 KB)
constexpr int SM_HS    = 81920;            // h bf16 [32][256] swizzled (16 KB)
constexpr int SM_B1    = 98304;            // b1 fp32 [1024]
constexpr int SM_B2    = 102400;           // b2 fp32 [1024]
constexpr int SM_WT    = 106496;           // gate weights [32][4] fp32
constexpr int SM_TOTAL = 107008;           // 104.5 KB -> 2 CTAs/SM
// gating-phase overlays (HS unused then)
constexpr int SM_GW    = SM_HS;            // gate_w fp32 [1024] (4 KB)
constexpr int SM_SP    = SM_HS + 4096;     // logit partials [8][32][4] (4 KB)
}  // namespace

__device__ __align__(16) unsigned char g_wimg[NSTAGE * STAGE_BYTES];

// ------------------------------ helpers -----------------------------------
__device__ __forceinline__ uint32_t smem_u32(const void* p) {
  uint32_t a;
  asm("{ .reg .u64 t; cvta.to.shared.u64 t, %1; cvt.u32.u64 %0, t; }"
      : "=r"(a) : "l"(p));
  return a;
}
__device__ __forceinline__ void ldsm4(uint32_t* r, uint32_t addr) {
  asm volatile("ldmatrix.sync.aligned.m8n8.x4.shared.b16 {%0,%1,%2,%3}, [%4];"
               : "=r"(r[0]), "=r"(r[1]), "=r"(r[2]), "=r"(r[3]) : "r"(addr));
}
__device__ __forceinline__ void mma16816(float* d, const uint32_t* a,
                                         const uint32_t* b) {
  asm volatile(
      "mma.sync.aligned.m16n8k16.row.col.f32.bf16.bf16.f32 "
      "{%0,%1,%2,%3}, {%4,%5,%6,%7}, {%8,%9}, {%0,%1,%2,%3};"
      : "+f"(d[0]), "+f"(d[1]), "+f"(d[2]), "+f"(d[3])
      : "r"(a[0]), "r"(a[1]), "r"(a[2]), "r"(a[3]), "r"(b[0]), "r"(b[1]));
}
__device__ __forceinline__ void cp16(uint32_t dst, const void* src) {
  asm volatile("cp.async.cg.shared.global [%0], [%1], 16;"
               :: "r"(dst), "l"(src));
}
__device__ __forceinline__ void cp_commit() {
  asm volatile("cp.async.commit_group;" ::: "memory");
}
template <int N>
__device__ __forceinline__ void cp_wait() {
  asm volatile("cp.async.wait_group %0;" :: "n"(N) : "memory");
}
__device__ __forceinline__ uint32_t pack_bf2(float a, float b) {
  __nv_bfloat162 t = __floats2bfloat162_rn(a, b);  // .x = a (low)
  return *reinterpret_cast<uint32_t*>(&t);
}

// One 64-k stage: warp tile M=32 (all tokens), N=32 (out-channels), K=64.
// A: smem bf16 [32 rows][256 k], 512B rows, swizzle kc^(row&7).
// B: stage buf [256 rows(n)][64 k], 128B rows, same swizzle.
__device__ __forceinline__ void run_stage(float (&acc)[2][4][4],
                                          uint32_t asrc, int kbase,
                                          uint32_t wbuf, int wn, int lane) {
  const int r  = lane & 7;
  const int mi = lane >> 3;
#pragma unroll
  for (int kq = 0; kq < 2; ++kq) {
    uint32_t a[2][2][4];
#pragma unroll
    for (int mt = 0; mt < 2; ++mt)
#pragma unroll
      for (int ks = 0; ks < 2; ++ks) {
        int row = mt * 16 + (mi & 1) * 8 + r;
        int kc  = (kbase >> 3) + (kq * 2 + ks) * 2 + (mi >> 1);
        ldsm4(a[mt][ks], asrc + row * 512 + ((kc ^ r) << 4));
      }
#pragma unroll
    for (int nt = 0; nt < 4; ++nt) {
      uint32_t b[4];
      int kc = kq * 4 + mi;
      ldsm4(b, wbuf + (wn * 32 + nt * 8 + r) * 128 + ((kc ^ r) << 4));
#pragma unroll
      for (int mt = 0; mt < 2; ++mt) {
        mma16816(acc[mt][nt], a[mt][0], b);
        mma16816(acc[mt][nt], a[mt][1], b + 2);
      }
    }
  }
}

// ---------------------------------------------------------------------------
// Prologue: bf16 swizzled weight images (32 stages x 256 rows x 64 k).
// ---------------------------------------------------------------------------
__global__ void prep_weights(const float* __restrict__ w1,
                             const float* __restrict__ w2) {
  int idx = blockIdx.x * blockDim.x + threadIdx.x;  // 65536 threads
  int s  = idx >> 11;          // stage (2048 uint4 per stage)
  int r  = (idx >> 3) & 255;   // row (out/hidden channel)
  int kc = idx & 7;            // 16B chunk within 64-k row
  int e = s >> 3, ph = s & 7;
  const float* src;
  if (ph < 4) src = w1 + (size_t)(e * 256 + r) * 256 + ph * 64 + kc * 8;
  else        src = w2 + (size_t)e * 65536 + (size_t)r * 256 + (ph - 4) * 64 + kc * 8;
  float4 v0 = *reinterpret_cast<const float4*>(src);
  float4 v1 = *reinterpret_cast<const float4*>(src + 4);
  uint4 pk;
  pk.x = pack_bf2(v0.x, v0.y);
  pk.y = pack_bf2(v0.z, v0.w);
  pk.z = pack_bf2(v1.x, v1.y);
  pk.w = pack_bf2(v1.z, v1.w);
  *reinterpret_cast<uint4*>(g_wimg + (size_t)s * STAGE_BYTES + r * 128 +
                            ((kc ^ (r & 7)) << 4)) = pk;
}

// ---------------------------------------------------------------------------
// Main fused kernel.
// ---------------------------------------------------------------------------
__global__ __launch_bounds__(NTHR, 2)
void moe_mma_kernel(const float* __restrict__ x,
                    const float* __restrict__ gate_w,
                    const float* __restrict__ gate_b,
                    const float* __restrict__ b1,
                    const float* __restrict__ b2,
                    float* __restrict__ out) {
  extern __shared__ __align__(16) unsigned char smraw[];
  const uint32_t smb = smem_u32(smraw);
  float* gws  = reinterpret_cast<float*>(smraw + SM_GW);
  float* b1s  = reinterpret_cast<float*>(smraw + SM_B1);
  float* b2s  = reinterpret_cast<float*>(smraw + SM_B2);
  float* sp   = reinterpret_cast<float*>(smraw + SM_SP);
  float* wts  = reinterpret_cast<float*>(smraw + SM_WT);

  const int tid  = threadIdx.x;
  const int lane = tid & 31;
  const int wn   = tid >> 5;   // 0..7: out-col block (32 cols)

  const int token0 = blockIdx.x * TM;
  const int bidx   = token0 / THW;
  const int s0     = token0 % THW;
  const float* xb = x   + (size_t)bidx * C * THW + s0;
  float*       ob = out + (size_t)bidx * C * THW + s0;

  // --- kick stage 0 weight copy immediately -------------------------------
  {
    const unsigned char* src = g_wimg;
#pragma unroll
    for (int it = 0; it < 8; ++it) {
      int off = it * 4096 + tid * 16;
      cp16(smb + SM_WBUF0 + off, src + off);
    }
    cp_commit();
  }

  // --- stage gate_w / b1 / b2 ---------------------------------------------
#pragma unroll
  for (int rr = 0; rr < 4; ++rr) {
    int i = rr * NTHR + tid;
    gws[i] = gate_w[i];
    b1s[i] = b1[i];
    b2s[i] = b2[i];
  }
  __syncthreads();

  // --- x staging (fp32->bf16, swizzled) + fp32 gate logit partials --------
  {
    const int t   = tid & 31;
    const int cpg = tid >> 5;  // 0..7
    float l[4] = {0.f, 0.f, 0.f, 0.f};
    const float* gx = xb + t;
#pragma unroll
    for (int it = 0; it < 16; ++it) {
      int c0 = it * 16 + cpg * 2;
      float v0 = __ldg(gx + (size_t)c0 * THW);
      float v1 = __ldg(gx + (size_t)(c0 + 1) * THW);
#pragma unroll
      for (int e = 0; e < 4; ++e)
        l[e] = fmaf(gws[e * 256 + c0], v0, fmaf(gws[e * 256 + c0 + 1], v1, l[e]));
      uint32_t pk = pack_bf2(v0, v1);
      uint32_t off = t * 512 + (((c0 >> 3) ^ (t & 7)) << 4) + (c0 & 7) * 2;
      *reinterpret_cast<uint32_t*>(smraw + SM_XS + off) = pk;
    }
#pragma unroll
    for (int e = 0; e < 4; ++e) sp[cpg * 128 + t * 4 + e] = l[e];
  }
  __syncthreads();

  // --- logits reduce + top-2 softmax --------------------------------------
  if (tid < 32) {
    float l[4];
#pragma unroll
    for (int e = 0; e < 4; ++e) {
      float s = __ldg(gate_b + e);
#pragma unroll
      for (int g = 0; g < 8; ++g) s += sp[g * 128 + tid * 4 + e];
      l[e] = s;
    }
    float v1 = l[0]; int i1 = 0;
    if (l[1] > v1) { v1 = l[1]; i1 = 1; }
    if (l[2] > v1) { v1 = l[2]; i1 = 2; }
    if (l[3] > v1) { v1 = l[3]; i1 = 3; }
    float v2 = -3.402823e38f; int i2 = 0;
#pragma unroll
    for (int e = 0; e < 4; ++e)
      if (e != i1 && l[e] > v2) { v2 = l[e]; i2 = e; }
    float e2  = __expf(v2 - v1);
    float inv = 1.0f / (1.0f + e2);
    wts[tid * 4 + 0] = 0.f; wts[tid * 4 + 1] = 0.f;
    wts[tid * 4 + 2] = 0.f; wts[tid * 4 + 3] = 0.f;
    wts[tid * 4 + i1] = inv;
    wts[tid * 4 + i2] = e2 * inv;
  }
  __syncthreads();   // also: gating overlays (gws/sp in HS) dead after this

  // --- main pipelined loop over 32 weight stages --------------------------
  float acc1[2][4][4], acc2[2][4][4];
#pragma unroll
  for (int mt = 0; mt < 2; ++mt)
#pragma unroll
    for (int nt = 0; nt < 4; ++nt)
#pragma unroll
      for (int j = 0; j < 4; ++j) acc2[mt][nt][j] = 0.f;

#pragma unroll 1
  for (int s = 0; s < NSTAGE; ++s) {
    if (s + 1 < NSTAGE) {  // prefetch next stage into the other buffer
      const unsigned char* src = g_wimg + (size_t)(s + 1) * STAGE_BYTES;
      uint32_t dst = smb + (((s + 1) & 1) ? SM_WBUF1 : SM_WBUF0);
#pragma unroll
      for (int it = 0; it < 8; ++it) {
        int off = it * 4096 + tid * 16;
        cp16(dst + off, src + off);
      }
      cp_commit();
      cp_wait<1>();
    } else {
      cp_wait<0>();
    }
    __syncthreads();

    const int ph = s & 7, e = s >> 3;
    const uint32_t wbuf = smb + ((s & 1) ? SM_WBUF1 : SM_WBUF0);

    if (ph < 4) {
      if (ph == 0) {
#pragma unroll
        for (int mt = 0; mt < 2; ++mt)
#pragma unroll
          for (int nt = 0; nt < 4; ++nt)
#pragma unroll
            for (int j = 0; j < 4; ++j) acc1[mt][nt][j] = 0.f;
      }
      run_stage(acc1, smb + SM_XS, ph * 64, wbuf, wn, lane);
      if (ph == 3) {
        // h epilogue: +b1, SiLU, x gate weight, pack bf16 -> hs
#pragma unroll
        for (int mt = 0; mt < 2; ++mt) {
          const int tok1 = mt * 16 + (lane >> 2);
          const int tok2 = tok1 + 8;
          const float wt1 = wts[tok1 * 4 + e];
          const float wt2 = wts[tok2 * 4 + e];
#pragma unroll
          for (int nt = 0; nt < 4; ++nt) {
            int n = wn * 32 + nt * 8 + (lane & 3) * 2;
            float ba = b1s[e * 256 + n], bb = b1s[e * 256 + n + 1];
            float h0 = acc1[mt][nt][0] + ba, h1 = acc1[mt][nt][1] + bb;
            float h2 = acc1[mt][nt][2] + ba, h3 = acc1[mt][nt][3] + bb;
            h0 = h0 * (1.0f / (1.0f + __expf(-h0))) * wt1;
            h1 = h1 * (1.0f / (1.0f + __expf(-h1))) * wt1;
            h2 = h2 * (1.0f / (1.0f + __expf(-h2))) * wt2;
            h3 = h3 * (1.0f / (1.0f + __expf(-h3))) * wt2;
            uint32_t o1 = tok1 * 512 + (((n >> 3) ^ (tok1 & 7)) << 4) + (n & 7) * 2;
            uint32_t o2 = tok2 * 512 + (((n >> 3) ^ (tok2 & 7)) << 4) + (n & 7) * 2;
            *reinterpret_cast<uint32_t*>(smraw + SM_HS + o1) = pack_bf2(h0, h1);
            *reinterpret_cast<uint32_t*>(smraw + SM_HS + o2) = pack_bf2(h2, h3);
          }
        }
      }
    } else {
      run_stage(acc2, smb + SM_HS, (ph - 4) * 64, wbuf, wn, lane);
    }
    __syncthreads();
  }

  // --- final epilogue: acc2 -> smem (coalescing relay) -> global ----------
  float* d2s = reinterpret_cast<float*>(smraw);  // overlays weight buffers
#pragma unroll
  for (int mt = 0; mt < 2; ++mt) {
    const int tok1 = mt * 16 + (lane >> 2);
    const int tok2 = tok1 + 8;
#pragma unroll
    for (int nt = 0; nt < 4; ++nt) {
      int n = wn * 32 + nt * 8 + (lane & 3) * 2;
      *reinterpret_cast<float2*>(d2s + tok1 * 258 + n) =
          make_float2(acc2[mt][nt][0], acc2[mt][nt][1]);
      *reinterpret_cast<float2*>(d2s + tok2 * 258 + n) =
          make_float2(acc2[mt][nt][2], acc2[mt][nt][3]);
    }
  }
  __syncthreads();
  {
    const int t  = tid & 31;
    const int cg = tid >> 5;   // 0..7
    const float w0 = wts[t * 4 + 0], w1w = wts[t * 4 + 1];
    const float w2w = wts[t * 4 + 2], w3 = wts[t * 4 + 3];
#pragma unroll 4
    for (int i = 0; i < 32; ++i) {
      int ch = i * 8 + cg;
      float v = d2s[t * 258 + ch]
              + w0  * b2s[ch]       + w1w * b2s[256 + ch]
              + w2w * b2s[512 + ch] + w3  * b2s[768 + ch]
              + __ldg(xb + (size_t)ch * THW + t);
      ob[(size_t)ch * THW + t] = v;
    }
  }
}

// ---------------------------------------------------------------------------
extern "C" void kernel_launch(void* const* d_in, const int* in_sizes, int n_in,
                              void* d_out, int out_size) {
  const float* x      = (const float*)d_in[0];
  const float* gate_w = (const float*)d_in[1];
  const float* gate_b = (const float*)d_in[2];
  const float* w1     = (const float*)d_in[3];
  const float* b1     = (const float*)d_in[4];
  const float* w2     = (const float*)d_in[5];
  const float* b2     = (const float*)d_in[6];
  float* out          = (float*)d_out;
  (void)in_sizes; (void)n_in; (void)out_size;

  prep_weights<<<256, 256>>>(w1, w2);

  cudaFuncSetAttribute(moe_mma_kernel,
                       cudaFuncAttributeMaxDynamicSharedMemorySize, SM_TOTAL);
  moe_mma_kernel<<<NCTA, NTHR, SM_TOTAL>>>(x, gate_w, gate_b, b1, b2, out);
}